// round 2
// baseline (speedup 1.0000x reference)
#include <cuda_runtime.h>
#include <cuda_bf16.h>
#include <math.h>

// Problem shape (fixed by reference):
//   x  : [B=64, T=512, D=512]  fp32
//   kz/kr/kh : [D=512, H=1024] fp32
//   mz/mr/br/bz : [H] fp32
//   out: [B, T, H] fp32
// Phase 1: xz/xr/xh = x @ k* (three GEMMs, M=B*T=32768, K=512, N=1024)
// Phase 2: diagonal recurrence scan over T per independent (b,h) channel.

#define Bsz 64
#define Tsz 512
#define Dsz 512
#define Hsz 1024
#define Msz (Bsz * Tsz)  // 32768

// Scratch for projections (static device arrays — no runtime allocation).
__device__ float g_xz[(size_t)Msz * Hsz];
__device__ float g_xr[(size_t)Msz * Hsz];
__device__ float g_xh[(size_t)Msz * Hsz];

// ---------------------------------------------------------------------------
// GEMM: Y[m][n] = sum_k X[m][k] * W[k][n]
// BM=128, BN=128, BK=16, 256 threads, 8x8 per-thread microtile.
// grid = (N/128, M/128, 3); blockIdx.z selects weight/output.
// ---------------------------------------------------------------------------
#define BM 128
#define BN 128
#define BK 16

__global__ __launch_bounds__(256, 2) void gemm3_kernel(
    const float* __restrict__ X,
    const float* __restrict__ Kz,
    const float* __restrict__ Kr,
    const float* __restrict__ Kh)
{
    const float* W = (blockIdx.z == 0) ? Kz : (blockIdx.z == 1) ? Kr : Kh;
    float* Y = (blockIdx.z == 0) ? g_xz : (blockIdx.z == 1) ? g_xr : g_xh;

    __shared__ float As[BK][BM];  // A stored transposed
    __shared__ float Bs[BK][BN];

    const int tid = threadIdx.x;
    const int block_row = blockIdx.y * BM;
    const int block_col = blockIdx.x * BN;

    const int ty = tid >> 4;        // 0..15
    const int tx = tid & 15;        // 0..15

    float acc[8][8];
#pragma unroll
    for (int i = 0; i < 8; i++)
#pragma unroll
        for (int j = 0; j < 8; j++)
            acc[i][j] = 0.0f;

    for (int k0 = 0; k0 < Dsz; k0 += BK) {
        // Load A tile: BM x BK = 2048 floats = 512 float4, 2 per thread.
#pragma unroll
        for (int l = 0; l < 2; l++) {
            int f  = tid + l * 256;
            int r  = f >> 2;            // 0..127
            int c4 = (f & 3) << 2;      // 0,4,8,12
            float4 v = *(const float4*)(X + (size_t)(block_row + r) * Dsz + k0 + c4);
            As[c4 + 0][r] = v.x;
            As[c4 + 1][r] = v.y;
            As[c4 + 2][r] = v.z;
            As[c4 + 3][r] = v.w;
        }
        // Load B tile: BK x BN = 2048 floats = 512 float4, 2 per thread.
#pragma unroll
        for (int l = 0; l < 2; l++) {
            int f  = tid + l * 256;
            int r  = f >> 5;            // 0..15
            int c4 = (f & 31) << 2;     // 0..124
            *(float4*)(&Bs[r][c4]) =
                *(const float4*)(W + (size_t)(k0 + r) * Hsz + block_col + c4);
        }
        __syncthreads();

#pragma unroll
        for (int kk = 0; kk < BK; kk++) {
            float a[8], b[8];
#pragma unroll
            for (int i = 0; i < 8; i++) a[i] = As[kk][ty * 8 + i];
#pragma unroll
            for (int j = 0; j < 8; j++) b[j] = Bs[kk][tx * 8 + j];
#pragma unroll
            for (int i = 0; i < 8; i++)
#pragma unroll
                for (int j = 0; j < 8; j++)
                    acc[i][j] = fmaf(a[i], b[j], acc[i][j]);
        }
        __syncthreads();
    }

    // Store 8x8 microtile.
#pragma unroll
    for (int i = 0; i < 8; i++) {
        float* yrow = Y + (size_t)(block_row + ty * 8 + i) * Hsz + block_col + tx * 8;
#pragma unroll
        for (int j = 0; j < 8; j += 4) {
            float4 v = make_float4(acc[i][j], acc[i][j + 1], acc[i][j + 2], acc[i][j + 3]);
            *(float4*)(yrow + j) = v;
        }
    }
}

// ---------------------------------------------------------------------------
// Scan: one thread per (b, i) channel; sequential over t.
//   r = tanh(xr + h*mr + br) + 1
//   z = sigmoid(xz + h*mz + bz)
//   h = z*h + (1-z)*tanh(xh + r*h)
// ---------------------------------------------------------------------------
__global__ __launch_bounds__(256) void scan_kernel(
    const float* __restrict__ mz,
    const float* __restrict__ mr,
    const float* __restrict__ br,
    const float* __restrict__ bz,
    float* __restrict__ out)
{
    const int idx = blockIdx.x * blockDim.x + threadIdx.x;  // 0..B*H-1
    const int b = idx >> 10;        // idx / H
    const int i = idx & (Hsz - 1);  // idx % H

    const float vmz = mz[i];
    const float vmr = mr[i];
    const float vbr = br[i];
    const float vbz = bz[i];

    float h = 0.0f;
    size_t off = (size_t)b * Tsz * Hsz + i;

#pragma unroll 4
    for (int t = 0; t < Tsz; t++) {
        const float pz = g_xz[off];
        const float pr = g_xr[off];
        const float ph = g_xh[off];

        const float r = tanhf(fmaf(h, vmr, pr) + vbr) + 1.0f;
        const float zarg = fmaf(h, vmz, pz) + vbz;
        const float z = 1.0f / (1.0f + __expf(-zarg));
        const float cand = tanhf(fmaf(r, h, ph));
        h = fmaf(z, h - cand, cand);  // z*h + (1-z)*cand

        out[off] = h;
        off += Hsz;
    }
}

// ---------------------------------------------------------------------------
extern "C" void kernel_launch(void* const* d_in, const int* in_sizes, int n_in,
                              void* d_out, int out_size)
{
    const float* x  = (const float*)d_in[0];
    const float* kz = (const float*)d_in[1];
    const float* kr = (const float*)d_in[2];
    const float* kh = (const float*)d_in[3];
    const float* mz = (const float*)d_in[4];
    const float* mr = (const float*)d_in[5];
    const float* br = (const float*)d_in[6];
    const float* bz = (const float*)d_in[7];
    float* out = (float*)d_out;

    dim3 ggrid(Hsz / BN, Msz / BM, 3);  // (8, 256, 3)
    gemm3_kernel<<<ggrid, 256>>>(x, kz, kr, kh);

    scan_kernel<<<(Bsz * Hsz) / 256, 256>>>(mz, mr, br, bz, out);
}

// round 4
// speedup vs baseline: 2.5333x; 2.5333x over previous
#include <cuda_runtime.h>
#include <cuda_bf16.h>
#include <math.h>
#include <stdint.h>

// Shapes (fixed): x[64,512,512] f32, k*[512,1024] f32, out[64,512,1024] f32
#define Bsz 64
#define Tsz 512
#define Dsz 512
#define Hsz 1024
#define Msz (Bsz * Tsz)   // 32768
#define KC  1536          // split-precision concatenated K: [hi | lo | hi]

// ---------------- device scratch (static, no runtime alloc) ----------------
__device__ float g_xz[(size_t)Msz * Hsz];
__device__ float g_xr[(size_t)Msz * Hsz];
__device__ float g_xh[(size_t)Msz * Hsz];
__device__ __align__(16) __nv_bfloat16 g_A[(size_t)Msz * KC];        // 96 MB
__device__ __align__(16) __nv_bfloat16 g_B[3][(size_t)Hsz * KC];     // 9 MB

// ---------------- PTX helpers (all base-sm_103 features) ----------------
__device__ __forceinline__ uint32_t smem_u32(const void* p) {
    uint32_t a;
    asm("{ .reg .u64 t; cvta.to.shared.u64 t, %1; cvt.u32.u64 %0, t; }" : "=r"(a) : "l"(p));
    return a;
}
__device__ __forceinline__ void cpasync16(uint32_t dst, const void* src) {
    asm volatile("cp.async.cg.shared.global [%0], [%1], 16;" :: "r"(dst), "l"(src) : "memory");
}
__device__ __forceinline__ void cp_commit() {
    asm volatile("cp.async.commit_group;" ::: "memory");
}
template <int N>
__device__ __forceinline__ void cp_wait() {
    asm volatile("cp.async.wait_group %0;" :: "n"(N) : "memory");
}
__device__ __forceinline__ void ldsm_x4(uint32_t& d0, uint32_t& d1, uint32_t& d2,
                                        uint32_t& d3, uint32_t addr) {
    asm volatile("ldmatrix.sync.aligned.m8n8.x4.shared.b16 {%0,%1,%2,%3}, [%4];"
                 : "=r"(d0), "=r"(d1), "=r"(d2), "=r"(d3) : "r"(addr));
}
__device__ __forceinline__ void ldsm_x2(uint32_t& d0, uint32_t& d1, uint32_t addr) {
    asm volatile("ldmatrix.sync.aligned.m8n8.x2.shared.b16 {%0,%1}, [%2];"
                 : "=r"(d0), "=r"(d1) : "r"(addr));
}
__device__ __forceinline__ void mma16816(float& c0, float& c1, float& c2, float& c3,
                                         uint32_t a0, uint32_t a1, uint32_t a2, uint32_t a3,
                                         uint32_t b0, uint32_t b1) {
    asm volatile(
        "mma.sync.aligned.m16n8k16.row.col.f32.bf16.bf16.f32 "
        "{%0,%1,%2,%3}, {%4,%5,%6,%7}, {%8,%9}, {%0,%1,%2,%3};"
        : "+f"(c0), "+f"(c1), "+f"(c2), "+f"(c3)
        : "r"(a0), "r"(a1), "r"(a2), "r"(a3), "r"(b0), "r"(b1));
}

// ---------------- conversion kernels ----------------
// A_cat[m][0:512]=bf16hi(x), [512:1024]=bf16lo(x), [1024:1536]=bf16hi(x)
__global__ __launch_bounds__(256) void convA_kernel(const float* __restrict__ x) {
    int idx = blockIdx.x * blockDim.x + threadIdx.x;       // Msz * 128 threads
    int m  = idx >> 7;
    int kg = (idx & 127) << 2;
    float4 v = *(const float4*)(x + (size_t)m * Dsz + kg);

    __nv_bfloat16 hi[4], lo[4];
    float vv[4] = {v.x, v.y, v.z, v.w};
#pragma unroll
    for (int j = 0; j < 4; j++) {
        hi[j] = __float2bfloat16(vv[j]);
        lo[j] = __float2bfloat16(vv[j] - __bfloat162float(hi[j]));
    }
    uint64_t hp, lp;
    memcpy(&hp, hi, 8);
    memcpy(&lp, lo, 8);
    __nv_bfloat16* row = g_A + (size_t)m * KC + kg;
    *(uint64_t*)(row)        = hp;
    *(uint64_t*)(row + 512)  = lp;
    *(uint64_t*)(row + 1024) = hp;
}

// B_cat[p][n][0:512]=bf16hi(W[:,n]), [512:1024]=hi, [1024:1536]=lo  (transposed)
__global__ __launch_bounds__(256) void convB_kernel(const float* __restrict__ kz,
                                                    const float* __restrict__ kr,
                                                    const float* __restrict__ kh) {
    int idx = blockIdx.x * blockDim.x + threadIdx.x;       // 3 * 1024 * 64 threads
    int proj = idx >> 16;
    int r    = idx & 65535;
    int n  = r >> 6;
    int kg = (r & 63) << 3;
    const float* W = (proj == 0) ? kz : (proj == 1) ? kr : kh;

    __nv_bfloat16 hi[8], lo[8];
#pragma unroll
    for (int j = 0; j < 8; j++) {
        float w = W[(size_t)(kg + j) * Hsz + n];
        hi[j] = __float2bfloat16(w);
        lo[j] = __float2bfloat16(w - __bfloat162float(hi[j]));
    }
    uint4 hp, lp;
    memcpy(&hp, hi, 16);
    memcpy(&lp, lo, 16);
    __nv_bfloat16* row = g_B[proj] + (size_t)n * KC + kg;
    *(uint4*)(row)        = hp;
    *(uint4*)(row + 512)  = hp;
    *(uint4*)(row + 1024) = lp;
}

// ---------------- mma.sync GEMM ----------------
// BM=128, BN=128, BK=32 bf16. 256 threads = 8 warps (2 m-groups x 4 n-groups),
// warp tile 64x32. 4-stage cp.async pipeline, ldmatrix operand fetch.
#define BKc 32
#define STAGES 4
#define NK (KC / BKc)                 // 48
#define STG_BYTES 16384               // A 8KB + B 8KB
#define EPI_PITCH 132
#define SMEM_BYTES (128 * EPI_PITCH * 4)   // 67584 > 4*16384

__global__ __launch_bounds__(256) void gemm_kernel() {
    extern __shared__ char smem[];
    const uint32_t sb = smem_u32(smem);
    const int tid  = threadIdx.x;
    const int lane = tid & 31;
    const int wid  = tid >> 5;
    const int wm   = wid & 1;        // m-group (0/1): rows wm*64..+63
    const int wn   = wid >> 1;       // n-group (0..3): cols wn*32..+31

    const int proj = blockIdx.x >> 3;
    const int n0   = (blockIdx.x & 7) * 128;
    const int m0   = blockIdx.y * 128;
    const __nv_bfloat16* Ag = g_A + (size_t)m0 * KC;
    const __nv_bfloat16* Bg = g_B[proj] + (size_t)n0 * KC;
    float* Y = (proj == 0) ? g_xz : (proj == 1) ? g_xr : g_xh;

    float acc[4][4][4];
#pragma unroll
    for (int i = 0; i < 4; i++)
#pragma unroll
        for (int j = 0; j < 4; j++)
#pragma unroll
            for (int c = 0; c < 4; c++) acc[i][j][c] = 0.0f;

    // stage loader: 1024 x 16B chunks (A 512, B 512), 4 per thread.
    auto load_stage = [&](int stage, int kit) {
        const int k0 = kit * BKc;
        const uint32_t stg = sb + stage * STG_BYTES;
#pragma unroll
        for (int l = 0; l < 4; l++) {
            int cid = l * 256 + tid;
            int isB = cid >> 9;
            int r   = (cid >> 2) & 127;
            int c   = cid & 3;
            const __nv_bfloat16* src = (isB ? Bg : Ag) + (size_t)r * KC + k0 + c * 8;
            int c_sw = c ^ ((r >> 1) & 3);
            uint32_t dst = stg + isB * 8192 + r * 64 + (c_sw << 4);
            cpasync16(dst, src);
        }
        cp_commit();
    };

    // prologue: STAGES-1 stages in flight
#pragma unroll
    for (int s = 0; s < STAGES - 1; s++) load_stage(s, s);

    // Precompute ldmatrix lane-row components.
    const int a_row_lane = lane & 15;          // within 16-row frag
    const int a_chunk_hi = lane >> 4;          // +0 / +1 chunk
    const int b_row_lane = lane & 7;
    const int b_chunk_hi = (lane >> 3) & 1;

    for (int kit = 0; kit < NK; kit++) {
        const int stage = kit & (STAGES - 1);
        const int rem = NK - 1 - kit;
        if (rem >= 2)      cp_wait<2>();
        else if (rem == 1) cp_wait<1>();
        else               cp_wait<0>();
        __syncthreads();

        if (kit + STAGES - 1 < NK)
            load_stage((kit + STAGES - 1) & (STAGES - 1), kit + STAGES - 1);

        const uint32_t abase = sb + stage * STG_BYTES;
        const uint32_t bbase = abase + 8192;

#pragma unroll
        for (int kk = 0; kk < 2; kk++) {
            uint32_t a[4][4], b[4][2];
#pragma unroll
            for (int i = 0; i < 4; i++) {
                int row = wm * 64 + i * 16 + a_row_lane;
                int c = kk * 2 + a_chunk_hi;
                int c_sw = c ^ ((row >> 1) & 3);
                ldsm_x4(a[i][0], a[i][1], a[i][2], a[i][3],
                        abase + row * 64 + (c_sw << 4));
            }
#pragma unroll
            for (int j = 0; j < 4; j++) {
                int row = wn * 32 + j * 8 + b_row_lane;
                int c = kk * 2 + b_chunk_hi;
                int c_sw = c ^ ((row >> 1) & 3);
                ldsm_x2(b[j][0], b[j][1], bbase + row * 64 + (c_sw << 4));
            }
#pragma unroll
            for (int i = 0; i < 4; i++)
#pragma unroll
                for (int j = 0; j < 4; j++)
                    mma16816(acc[i][j][0], acc[i][j][1], acc[i][j][2], acc[i][j][3],
                             a[i][0], a[i][1], a[i][2], a[i][3], b[j][0], b[j][1]);
        }
    }

    // ---- epilogue: fragments -> padded smem -> coalesced float4 stores ----
    __syncthreads();
    float* so = (float*)smem;
    const int qr = lane >> 2;     // 0..7
    const int qc = lane & 3;      // 0..3
#pragma unroll
    for (int i = 0; i < 4; i++) {
#pragma unroll
        for (int j = 0; j < 4; j++) {
            int r0 = wm * 64 + i * 16 + qr;
            int cc = wn * 32 + j * 8 + qc * 2;
            *(float2*)(so + r0 * EPI_PITCH + cc)       = make_float2(acc[i][j][0], acc[i][j][1]);
            *(float2*)(so + (r0 + 8) * EPI_PITCH + cc) = make_float2(acc[i][j][2], acc[i][j][3]);
        }
    }
    __syncthreads();

#pragma unroll
    for (int p = 0; p < 16; p++) {
        int row = p * 8 + (tid >> 5);
        int c4  = (tid & 31) << 2;
        const float* s = so + row * EPI_PITCH + c4;
        float4 v = make_float4(s[0], s[1], s[2], s[3]);
        *(float4*)(Y + (size_t)(m0 + row) * Hsz + n0 + c4) = v;
    }
}

// ---------------- scan (diagonal recurrence) ----------------
__device__ __forceinline__ float fast_tanh(float a) {
    float e = __expf(2.0f * a);
    return 1.0f - __fdividef(2.0f, e + 1.0f);   // saturates correctly at +/-1
}

__global__ __launch_bounds__(256) void scan_kernel(
    const float* __restrict__ mz, const float* __restrict__ mr,
    const float* __restrict__ br, const float* __restrict__ bz,
    float* __restrict__ out)
{
    const int idx = blockIdx.x * blockDim.x + threadIdx.x;  // B*H threads
    const int b = idx >> 10;
    const int i = idx & (Hsz - 1);

    const float vmz = mz[i], vmr = mr[i], vbr = br[i], vbz = bz[i];

    const size_t base = (size_t)b * Tsz * Hsz + i;
    const float* gz = g_xz;
    const float* gr = g_xr;
    const float* gh = g_xh;

    const int PF = 4;                 // 12 independent loads in flight
    float az[PF], ar[PF], ah[PF];
#pragma unroll
    for (int p = 0; p < PF; p++) {
        size_t o = base + (size_t)p * Hsz;
        az[p] = __ldcs(gz + o);
        ar[p] = __ldcs(gr + o);
        ah[p] = __ldcs(gh + o);
    }

    float h = 0.0f;
    size_t off = base;
    for (int t0 = 0; t0 < Tsz; t0 += PF) {
#pragma unroll
        for (int p = 0; p < PF; p++) {
            const float pz = az[p], pr = ar[p], ph = ah[p];
            if (t0 + p + PF < Tsz) {
                size_t noff = off + (size_t)PF * Hsz;
                az[p] = __ldcs(gz + noff);
                ar[p] = __ldcs(gr + noff);
                ah[p] = __ldcs(gh + noff);
            }
            const float r    = fast_tanh(fmaf(h, vmr, pr) + vbr) + 1.0f;
            const float zarg = fmaf(h, vmz, pz) + vbz;
            const float z    = __fdividef(1.0f, 1.0f + __expf(-zarg));
            const float cand = fast_tanh(fmaf(r, h, ph));
            h = fmaf(z, h - cand, cand);
            out[off] = h;
            off += Hsz;
        }
    }
}

// ---------------- launch ----------------
extern "C" void kernel_launch(void* const* d_in, const int* in_sizes, int n_in,
                              void* d_out, int out_size)
{
    const float* x  = (const float*)d_in[0];
    const float* kz = (const float*)d_in[1];
    const float* kr = (const float*)d_in[2];
    const float* kh = (const float*)d_in[3];
    const float* mz = (const float*)d_in[4];
    const float* mr = (const float*)d_in[5];
    const float* br = (const float*)d_in[6];
    const float* bz = (const float*)d_in[7];
    float* out = (float*)d_out;

    cudaFuncSetAttribute(gemm_kernel, cudaFuncAttributeMaxDynamicSharedMemorySize,
                         SMEM_BYTES);

    convA_kernel<<<(Msz * 128) / 256, 256>>>(x);
    convB_kernel<<<(3 * Hsz * 64) / 256, 256>>>(kz, kr, kh);

    gemm_kernel<<<dim3(24, 256), 256, SMEM_BYTES>>>();

    scan_kernel<<<(Bsz * Hsz) / 256, 256>>>(mz, mr, br, bz, out);
}

// round 5
// speedup vs baseline: 2.5797x; 1.0183x over previous
#include <cuda_runtime.h>
#include <cuda_bf16.h>
#include <math.h>
#include <stdint.h>

// Shapes (fixed): x[64,512,512] f32, k*[512,1024] f32, out[64,512,1024] f32
#define Bsz 64
#define Tsz 512
#define Dsz 512
#define Hsz 1024
#define Msz (Bsz * Tsz)   // 32768
#define KCB 1536          // B concat K: [whi | whi | wlo]
#define KCA 1024          // A concat K: [xhi | xlo]  (3rd term re-reads xhi)

// ---------------- device scratch (static, no runtime alloc) ----------------
__device__ float g_xz[(size_t)Msz * Hsz];
__device__ float g_xr[(size_t)Msz * Hsz];
__device__ float g_xh[(size_t)Msz * Hsz];
__device__ __align__(16) __nv_bfloat16 g_A[(size_t)Msz * KCA];       // 64 MB
__device__ __align__(16) __nv_bfloat16 g_B[3][(size_t)Hsz * KCB];    // 9 MB

// ---------------- PTX helpers (base-sm_103 features only) ----------------
__device__ __forceinline__ uint32_t smem_u32(const void* p) {
    uint32_t a;
    asm("{ .reg .u64 t; cvta.to.shared.u64 t, %1; cvt.u32.u64 %0, t; }" : "=r"(a) : "l"(p));
    return a;
}
__device__ __forceinline__ void cpasync16(uint32_t dst, const void* src) {
    asm volatile("cp.async.cg.shared.global [%0], [%1], 16;" :: "r"(dst), "l"(src) : "memory");
}
__device__ __forceinline__ void cp_commit() {
    asm volatile("cp.async.commit_group;" ::: "memory");
}
template <int N>
__device__ __forceinline__ void cp_wait() {
    asm volatile("cp.async.wait_group %0;" :: "n"(N) : "memory");
}
__device__ __forceinline__ void ldsm_x4(uint32_t& d0, uint32_t& d1, uint32_t& d2,
                                        uint32_t& d3, uint32_t addr) {
    asm volatile("ldmatrix.sync.aligned.m8n8.x4.shared.b16 {%0,%1,%2,%3}, [%4];"
                 : "=r"(d0), "=r"(d1), "=r"(d2), "=r"(d3) : "r"(addr));
}
__device__ __forceinline__ void ldsm_x2(uint32_t& d0, uint32_t& d1, uint32_t addr) {
    asm volatile("ldmatrix.sync.aligned.m8n8.x2.shared.b16 {%0,%1}, [%2];"
                 : "=r"(d0), "=r"(d1) : "r"(addr));
}
__device__ __forceinline__ void mma16816(float& c0, float& c1, float& c2, float& c3,
                                         uint32_t a0, uint32_t a1, uint32_t a2, uint32_t a3,
                                         uint32_t b0, uint32_t b1) {
    asm volatile(
        "mma.sync.aligned.m16n8k16.row.col.f32.bf16.bf16.f32 "
        "{%0,%1,%2,%3}, {%4,%5,%6,%7}, {%8,%9}, {%0,%1,%2,%3};"
        : "+f"(c0), "+f"(c1), "+f"(c2), "+f"(c3)
        : "r"(a0), "r"(a1), "r"(a2), "r"(a3), "r"(b0), "r"(b1));
}

// ---------------- conversion kernels ----------------
// A: [m][0:512]=bf16hi(x), [512:1024]=bf16lo(x)
__global__ __launch_bounds__(256) void convA_kernel(const float* __restrict__ x) {
    int idx = blockIdx.x * blockDim.x + threadIdx.x;       // Msz*128 threads
    int m  = idx >> 7;
    int kg = (idx & 127) << 2;
    float4 v = *(const float4*)(x + (size_t)m * Dsz + kg);

    __nv_bfloat16 hi[4], lo[4];
    float vv[4] = {v.x, v.y, v.z, v.w};
#pragma unroll
    for (int j = 0; j < 4; j++) {
        hi[j] = __float2bfloat16(vv[j]);
        lo[j] = __float2bfloat16(vv[j] - __bfloat162float(hi[j]));
    }
    uint64_t hp, lp;
    memcpy(&hp, hi, 8);
    memcpy(&lp, lo, 8);
    __nv_bfloat16* row = g_A + (size_t)m * KCA + kg;
    *(uint64_t*)(row)       = hp;
    *(uint64_t*)(row + 512) = lp;
}

// B: [p][n][0:512]=bf16hi(W[:,n]), [512:1024]=hi, [1024:1536]=lo (transposed)
__global__ __launch_bounds__(256) void convB_kernel(const float* __restrict__ kz,
                                                    const float* __restrict__ kr,
                                                    const float* __restrict__ kh) {
    int idx = blockIdx.x * blockDim.x + threadIdx.x;       // 3*1024*64 threads
    int proj = idx >> 16;
    int r    = idx & 65535;
    int n  = r >> 6;
    int kg = (r & 63) << 3;
    const float* W = (proj == 0) ? kz : (proj == 1) ? kr : kh;

    __nv_bfloat16 hi[8], lo[8];
#pragma unroll
    for (int j = 0; j < 8; j++) {
        float w = W[(size_t)(kg + j) * Hsz + n];
        hi[j] = __float2bfloat16(w);
        lo[j] = __float2bfloat16(w - __bfloat162float(hi[j]));
    }
    uint4 hp, lp;
    memcpy(&hp, hi, 16);
    memcpy(&lp, lo, 16);
    __nv_bfloat16* row = g_B[proj] + (size_t)n * KCB + kg;
    *(uint4*)(row)        = hp;
    *(uint4*)(row + 512)  = hp;
    *(uint4*)(row + 1024) = lp;
}

// ---------------- mma.sync GEMM ----------------
// BM=256, BN=128, BK=64. 512 threads = 16 warps (4m x 4n), warp tile 64x32.
// 3-stage cp.async pipeline (48KB/stage), SW128-style smem swizzle.
#define BKc 64
#define STAGES 3
#define NK (KCB / BKc)                  // 24
#define A_STG 32768                     // 256 rows * 128B
#define B_STG 16384                     // 128 rows * 128B
#define STG_BYTES (A_STG + B_STG)       // 49152
#define EPI_PITCH 132
#define SMEM_BYTES (STAGES * STG_BYTES) // 147456 (> epilogue 67584)

__global__ __launch_bounds__(512, 1) void gemm_kernel() {
    extern __shared__ char smem[];
    const uint32_t sb = smem_u32(smem);
    const int tid  = threadIdx.x;
    const int lane = tid & 31;
    const int wid  = tid >> 5;
    const int wm   = wid & 3;        // rows wm*64..+63
    const int wn   = wid >> 2;       // cols wn*32..+31

    const int proj = blockIdx.x >> 3;
    const int n0   = (blockIdx.x & 7) * 128;
    const int m0   = blockIdx.y * 256;
    const __nv_bfloat16* Ag = g_A + (size_t)m0 * KCA;
    const __nv_bfloat16* Bg = g_B[proj] + (size_t)n0 * KCB;
    float* Y = (proj == 0) ? g_xz : (proj == 1) ? g_xr : g_xh;

    float acc[4][4][4];
#pragma unroll
    for (int i = 0; i < 4; i++)
#pragma unroll
        for (int j = 0; j < 4; j++)
#pragma unroll
            for (int c = 0; c < 4; c++) acc[i][j][c] = 0.0f;

    // stage loader: 3072 x 16B chunks (A 2048, B 1024), 6 per thread.
    auto load_stage = [&](int stage, int kit) {
        const int a_k0 = (kit >= 16 ? kit - 16 : kit) * BKc;  // wrap 3rd term to hi
        const int b_k0 = kit * BKc;
        const uint32_t stg = sb + stage * STG_BYTES;
#pragma unroll
        for (int l = 0; l < 6; l++) {
            int cid = l * 512 + tid;
            if (cid < 2048) {
                int r = cid >> 3, c = cid & 7;
                cpasync16(stg + r * 128 + ((c ^ (r & 7)) << 4),
                          Ag + (size_t)r * KCA + a_k0 + c * 8);
            } else {
                int cid2 = cid - 2048;
                int r = cid2 >> 3, c = cid2 & 7;
                cpasync16(stg + A_STG + r * 128 + ((c ^ (r & 7)) << 4),
                          Bg + (size_t)r * KCB + b_k0 + c * 8);
            }
        }
        cp_commit();
    };

    load_stage(0, 0);
    load_stage(1, 1);

    const int a_row_lane = lane & 15;
    const int a_chunk_hi = lane >> 4;
    const int b_row_lane = lane & 7;
    const int b_chunk_hi = (lane >> 3) & 1;

    for (int kit = 0; kit < NK; kit++) {
        const int stage = kit % STAGES;
        if (kit == NK - 1) cp_wait<0>(); else cp_wait<1>();
        __syncthreads();

        if (kit + 2 < NK) load_stage((kit + 2) % STAGES, kit + 2);

        const uint32_t abase = sb + stage * STG_BYTES;
        const uint32_t bbase = abase + A_STG;

#pragma unroll
        for (int kk = 0; kk < 4; kk++) {                 // 4 x K=16
            uint32_t a[4][4], b[4][2];
#pragma unroll
            for (int i = 0; i < 4; i++) {
                int row = wm * 64 + i * 16 + a_row_lane;
                int c = kk * 2 + a_chunk_hi;
                ldsm_x4(a[i][0], a[i][1], a[i][2], a[i][3],
                        abase + row * 128 + ((c ^ (row & 7)) << 4));
            }
#pragma unroll
            for (int j = 0; j < 4; j++) {
                int row = wn * 32 + j * 8 + b_row_lane;
                int c = kk * 2 + b_chunk_hi;
                ldsm_x2(b[j][0], b[j][1],
                        bbase + row * 128 + ((c ^ (row & 7)) << 4));
            }
#pragma unroll
            for (int i = 0; i < 4; i++)
#pragma unroll
                for (int j = 0; j < 4; j++)
                    mma16816(acc[i][j][0], acc[i][j][1], acc[i][j][2], acc[i][j][3],
                             a[i][0], a[i][1], a[i][2], a[i][3], b[j][0], b[j][1]);
        }
    }

    // ---- epilogue: fragments -> padded smem -> coalesced float4 stores ----
    __syncthreads();
    float* so = (float*)smem;
    const int qr = lane >> 2;
    const int qc = lane & 3;
#pragma unroll 1
    for (int half = 0; half < 2; half++) {       // m rows [half*128, +128)
        if ((wm >> 1) == half) {
            int lm = wm & 1;                      // 0/1 within half
#pragma unroll
            for (int i = 0; i < 4; i++) {
#pragma unroll
                for (int j = 0; j < 4; j++) {
                    int r0 = lm * 64 + i * 16 + qr;
                    int cc = wn * 32 + j * 8 + qc * 2;
                    *(float2*)(so + r0 * EPI_PITCH + cc) =
                        make_float2(acc[i][j][0], acc[i][j][1]);
                    *(float2*)(so + (r0 + 8) * EPI_PITCH + cc) =
                        make_float2(acc[i][j][2], acc[i][j][3]);
                }
            }
        }
        __syncthreads();
#pragma unroll
        for (int p = 0; p < 8; p++) {
            int row = p * 16 + (tid >> 5);
            int c4  = (tid & 31) << 2;
            const float* s = so + row * EPI_PITCH + c4;
            float4 v = make_float4(s[0], s[1], s[2], s[3]);
            *(float4*)(Y + (size_t)(m0 + half * 128 + row) * Hsz + n0 + c4) = v;
        }
        __syncthreads();
    }
}

// ---------------- scan (diagonal recurrence), 4 channels/thread ----------------
__device__ __forceinline__ float fast_tanh(float a) {
    float e = __expf(2.0f * a);
    return 1.0f - __fdividef(2.0f, e + 1.0f);
}

__global__ __launch_bounds__(256) void scan_kernel(
    const float* __restrict__ mz, const float* __restrict__ mr,
    const float* __restrict__ br, const float* __restrict__ bz,
    float* __restrict__ out)
{
    const int idx = blockIdx.x * blockDim.x + threadIdx.x;  // B*H/4 = 16384
    const int b  = idx >> 8;
    const int i4 = (idx & 255) << 2;

    const float4 vmz = *(const float4*)(mz + i4);
    const float4 vmr = *(const float4*)(mr + i4);
    const float4 vbr = *(const float4*)(br + i4);
    const float4 vbz = *(const float4*)(bz + i4);
    const float pmz[4] = {vmz.x, vmz.y, vmz.z, vmz.w};
    const float pmr[4] = {vmr.x, vmr.y, vmr.z, vmr.w};
    const float pbr[4] = {vbr.x, vbr.y, vbr.z, vbr.w};
    const float pbz[4] = {vbz.x, vbz.y, vbz.z, vbz.w};

    const size_t base = (size_t)b * Tsz * Hsz + i4;
    const float4* gz = (const float4*)g_xz;
    const float4* gr = (const float4*)g_xr;
    const float4* gh = (const float4*)g_xh;

    const int PF = 4;
    float4 az[PF], ar[PF], ah[PF];
#pragma unroll
    for (int p = 0; p < PF; p++) {
        size_t o = (base + (size_t)p * Hsz) >> 2;
        az[p] = __ldcs(gz + o);
        ar[p] = __ldcs(gr + o);
        ah[p] = __ldcs(gh + o);
    }

    float h[4] = {0.0f, 0.0f, 0.0f, 0.0f};
    size_t off = base;
    for (int t0 = 0; t0 < Tsz; t0 += PF) {
#pragma unroll
        for (int p = 0; p < PF; p++) {
            float pz[4] = {az[p].x, az[p].y, az[p].z, az[p].w};
            float pr[4] = {ar[p].x, ar[p].y, ar[p].z, ar[p].w};
            float ph[4] = {ah[p].x, ah[p].y, ah[p].z, ah[p].w};
            if (t0 + p + PF < Tsz) {
                size_t no = (off + (size_t)PF * Hsz) >> 2;
                az[p] = __ldcs(gz + no);
                ar[p] = __ldcs(gr + no);
                ah[p] = __ldcs(gh + no);
            }
            float4 o4;
            float* oo = (float*)&o4;
#pragma unroll
            for (int c = 0; c < 4; c++) {
                const float r    = fast_tanh(fmaf(h[c], pmr[c], pr[c]) + pbr[c]) + 1.0f;
                const float zarg = fmaf(h[c], pmz[c], pz[c]) + pbz[c];
                const float z    = __fdividef(1.0f, 1.0f + __expf(-zarg));
                const float cand = fast_tanh(fmaf(r, h[c], ph[c]));
                h[c] = fmaf(z, h[c] - cand, cand);
                oo[c] = h[c];
            }
            __stcs((float4*)(out + off), o4);
            off += Hsz;
        }
    }
}

// ---------------- launch ----------------
extern "C" void kernel_launch(void* const* d_in, const int* in_sizes, int n_in,
                              void* d_out, int out_size)
{
    const float* x  = (const float*)d_in[0];
    const float* kz = (const float*)d_in[1];
    const float* kr = (const float*)d_in[2];
    const float* kh = (const float*)d_in[3];
    const float* mz = (const float*)d_in[4];
    const float* mr = (const float*)d_in[5];
    const float* br = (const float*)d_in[6];
    const float* bz = (const float*)d_in[7];
    float* out = (float*)d_out;

    cudaFuncSetAttribute(gemm_kernel, cudaFuncAttributeMaxDynamicSharedMemorySize,
                         SMEM_BYTES);

    convA_kernel<<<(Msz * 128) / 256, 256>>>(x);
    convB_kernel<<<(3 * Hsz * 64) / 256, 256>>>(kz, kr, kh);

    gemm_kernel<<<dim3(24, 128), 512, SMEM_BYTES>>>();

    scan_kernel<<<(Bsz * Hsz / 4) / 256, 256>>>(mz, mr, br, bz, out);
}